// round 3
// baseline (speedup 1.0000x reference)
#include <cuda_runtime.h>
#include <cuda_fp16.h>
#include <cstdint>

// ---------------- problem constants ----------------
#define K_ORIG  20000
#define K_PAD   20032
#define M_TOTAL 2048
#define N_TOTAL 512
#define MT 128
#define NT 64
#define KT 64
#define NCHUNK (K_PAD / KT)      // 313

// ---------------- smem layout ----------------
#define A32_STRIDE 272                       // 256B row + 16B pad
#define A32_STAGE  (MT * A32_STRIDE)         // 34816
#define A16_BYTES  (MT * KT * 2)             // 16384
#define B_BYTES    (NT * KT * 2)             // 8192
#define A32_OFF    0
#define A16_OFF    (3 * A32_STAGE)           // 104448
#define B_OFF      (A16_OFF + 2 * A16_BYTES) // 137216
#define SMEM_TOTAL (B_OFF + 4 * B_BYTES)     // 169984
#define SMEM_BYTES (1024 + SMEM_TOTAL)

// ---------------- device scratch ----------------
__device__ __half g_eh[(size_t)N_TOTAL * K_PAD];   // E^T [N, K_PAD] K-major fp16

// ---------------- helpers ----------------
__device__ __forceinline__ uint32_t smem_u32(const void* p) {
    uint32_t a;
    asm("{ .reg .u64 t; cvta.to.shared.u64 t, %1; cvt.u32.u64 %0, t; }"
        : "=r"(a) : "l"(p));
    return a;
}

__device__ __forceinline__ uint32_t swz(uint32_t off) {
    return off ^ ((off >> 3) & 0x70u);     // 128B-period XOR swizzle
}

__device__ __forceinline__ void cp16(uint32_t sa, const void* gp) {
    asm volatile("cp.async.cg.shared.global [%0], [%1], 16;" :: "r"(sa), "l"(gp));
}

__device__ __forceinline__ void cp16z(uint32_t sa, const void* gp, int zf) {
    asm volatile("cp.async.cg.shared.global [%0], [%1], 16, %2;"
                 :: "r"(sa), "l"(gp), "r"(zf));
}

__device__ __forceinline__ void ldsm4(uint32_t* r, uint32_t sa) {
    asm volatile("ldmatrix.sync.aligned.m8n8.x4.shared.b16 {%0,%1,%2,%3}, [%4];"
                 : "=r"(r[0]), "=r"(r[1]), "=r"(r[2]), "=r"(r[3]) : "r"(sa));
}

__device__ __forceinline__ void mma16816(float* d, const uint32_t* a,
                                         const uint32_t* b) {
    asm volatile(
        "mma.sync.aligned.m16n8k16.row.col.f32.f16.f16.f32 "
        "{%0,%1,%2,%3}, {%4,%5,%6,%7}, {%8,%9}, {%0,%1,%2,%3};"
        : "+f"(d[0]), "+f"(d[1]), "+f"(d[2]), "+f"(d[3])
        : "r"(a[0]), "r"(a[1]), "r"(a[2]), "r"(a[3]), "r"(b[0]), "r"(b[1]));
}

__device__ __forceinline__ void lds_f4(float4& v, uint32_t a) {
    asm volatile("ld.shared.v4.f32 {%0,%1,%2,%3}, [%4];"
                 : "=f"(v.x), "=f"(v.y), "=f"(v.z), "=f"(v.w) : "r"(a));
}

__device__ __forceinline__ void sts16(uint32_t a, uint32_t r0, uint32_t r1,
                                      uint32_t r2, uint32_t r3) {
    asm volatile("st.shared.v4.b32 [%0], {%1,%2,%3,%4};"
                 :: "r"(a), "r"(r0), "r"(r1), "r"(r2), "r"(r3) : "memory");
}

__device__ __forceinline__ uint32_t pk2(float a, float b) {
    __half2 h = __floats2half2_rn(a, b);
    return *reinterpret_cast<uint32_t*>(&h);
}

// ---------------- E transpose+convert (kept: tiny, read 16x by GEMM) ----------
__global__ void convert_e_kernel(const float* __restrict__ e) {
    __shared__ float tile[32][33];
    const int kb = blockIdx.x * 32;
    const int hb = blockIdx.y * 32;
    const int tx = threadIdx.x, ty = threadIdx.y;
    #pragma unroll
    for (int i = ty; i < 32; i += 8) {
        int k = kb + i;
        tile[i][tx] = (k < K_ORIG) ? e[(size_t)k * N_TOTAL + hb + tx] : 0.0f;
    }
    __syncthreads();
    #pragma unroll
    for (int i = ty; i < 32; i += 8) {
        int h = hb + i;
        int k = kb + tx;
        g_eh[(size_t)h * K_PAD + k] = __float2half_rn(tile[tx][i]);
    }
}

// ---------------- fused fp16 mma.sync GEMM (A converted in-kernel) ----------
// out[m, n] = (sum_k x[m,k] * E[k,n]) / K_ORIG + bias[n]
__global__ void __launch_bounds__(256, 1)
gemm_fused_kernel(const float* __restrict__ x, const float* __restrict__ bias,
                  float* __restrict__ out) {
    extern __shared__ char smem_raw[];
    uint32_t sb = smem_u32(smem_raw);
    sb = (sb + 1023u) & ~1023u;

    const int tid = threadIdx.x;
    const int wid = tid >> 5;
    const int lid = tid & 31;
    const int m0 = blockIdx.x * MT;
    const int n0 = blockIdx.y * NT;

    const float* __restrict__ xg = x + (size_t)m0 * K_ORIG;
    const __half* __restrict__ eg = g_eh + (size_t)n0 * K_PAD;

    const uint32_t a32_base = sb + A32_OFF;
    const uint32_t a16_base = sb + A16_OFF;
    const uint32_t b_base   = sb + B_OFF;

    // ---- producer: A fp32 (zfill past K_ORIG) + B fp16 ----
    const int a_seg = tid & 15;          // 16B segment within 256B fp32 row
    const int a_r16 = tid >> 4;          // 0..15
    const int b_c16 = tid & 7;
    const int b_r32 = tid >> 3;          // 0..31

    auto load_chunk = [&](int c) {
        if (c >= NCHUNK) return;
        const int k0 = c * KT;
        const uint32_t sa32 = a32_base + (uint32_t)(c % 3) * (uint32_t)A32_STAGE;
        const int kk = k0 + a_seg * 4;
        const int zf = (kk < K_ORIG) ? 16 : 0;
        #pragma unroll
        for (int p = 0; p < 8; p++) {          // A: 128 rows of 256B
            const int row = a_r16 + p * 16;
            const uint32_t dst = sa32 + (uint32_t)(row * A32_STRIDE + a_seg * 16);
            cp16z(dst, xg + (size_t)row * K_ORIG + kk, zf);
        }
        const uint32_t sb16 = b_base + (uint32_t)(c & 3) * (uint32_t)B_BYTES;
        #pragma unroll
        for (int i = 0; i < 2; i++) {          // B: 64 rows of 128B
            const int row = b_r32 + i * 32;
            const uint32_t dst = sb16 + swz((uint32_t)(row * 128 + b_c16 * 16));
            cp16(dst, eg + (size_t)row * K_PAD + (k0 + b_c16 * 8));
        }
        asm volatile("cp.async.commit_group;" ::: "memory");
    };

    // ---- converter: fp32 stage -> swizzled fp16 tile (one pass per ks) ----
    const int cv_s = tid & 7;            // fp16 16B segment (8 halves)
    const int cv_r = tid >> 3;           // 0..31, +32 per pass
    auto convert_pass = [&](int c1, int p) {
        const uint32_t src = a32_base + (uint32_t)(c1 % 3) * (uint32_t)A32_STAGE;
        const uint32_t dst = a16_base + (uint32_t)(c1 & 1) * (uint32_t)A16_BYTES;
        const int r = cv_r + p * 32;
        float4 v0, v1;
        const uint32_t sa = src + (uint32_t)(r * A32_STRIDE + cv_s * 32);
        lds_f4(v0, sa);
        lds_f4(v1, sa + 16u);
        sts16(dst + swz((uint32_t)(r * 128 + cv_s * 16)),
              pk2(v0.x, v0.y), pk2(v0.z, v0.w), pk2(v1.x, v1.y), pk2(v1.z, v1.w));
    };

    // ---- consumer indexing (unchanged from passing kernel) ----
    const int wm = wid & 3;
    const int wn = wid >> 2;
    const int mbase = wm * 32;
    const int nbase = wn * 32;
    const int a_row = mbase + (lid & 15);
    const uint32_t a_kh = (uint32_t)(lid >> 4) * 16u;
    const int b_row = nbase + ((lid >> 4) * 8) + (lid & 7);
    const uint32_t b_kh = (uint32_t)((lid >> 3) & 1) * 16u;

    float acc[2][4][4];
    #pragma unroll
    for (int i = 0; i < 2; i++)
        #pragma unroll
        for (int j = 0; j < 4; j++)
            #pragma unroll
            for (int q = 0; q < 4; q++) acc[i][j][q] = 0.0f;

    // ---- preamble: chunks 0..2 in flight; chunk 0 converted ----
    load_chunk(0);
    load_chunk(1);
    load_chunk(2);
    asm volatile("cp.async.wait_group 2;" ::: "memory");
    __syncthreads();
    #pragma unroll
    for (int p = 0; p < 4; p++) convert_pass(0, p);
    asm volatile("cp.async.wait_group 1;" ::: "memory");
    __syncthreads();

    // ---- main loop: one __syncthreads per chunk ----
    for (int c = 0; c < NCHUNK; c++) {
        load_chunk(c + 3);

        const uint32_t a16 = a16_base + (uint32_t)(c & 1) * (uint32_t)A16_BYTES;
        const uint32_t btl = b_base + (uint32_t)(c & 3) * (uint32_t)B_BYTES;
        const bool do_cvt = (c + 1 < NCHUNK);

        #pragma unroll
        for (int ks = 0; ks < 4; ks++) {
            const uint32_t kb = (uint32_t)ks * 32u;
            uint32_t af[2][4];
            #pragma unroll
            for (int im = 0; im < 2; im++) {
                const uint32_t off = (uint32_t)((a_row + im * 16) * 128) + kb + a_kh;
                ldsm4(af[im], a16 + swz(off));
            }
            uint32_t bf[2][4];
            #pragma unroll
            for (int ib = 0; ib < 2; ib++) {
                const uint32_t off = (uint32_t)((b_row + ib * 16) * 128) + kb + b_kh;
                ldsm4(bf[ib], btl + swz(off));
            }
            #pragma unroll
            for (int im = 0; im < 2; im++) {
                #pragma unroll
                for (int in = 0; in < 4; in++) {
                    mma16816(acc[im][in], af[im], &bf[in >> 1][(in & 1) * 2]);
                }
            }
            if (do_cvt) convert_pass(c + 1, ks);   // hides in HMMA pipe gaps
        }

        if (c + 3 < NCHUNK) {
            asm volatile("cp.async.wait_group 1;" ::: "memory");
        } else {
            asm volatile("cp.async.wait_group 0;" ::: "memory");
        }
        __syncthreads();
    }

    // ---- epilogue ----
    const float inv = 1.0f / (float)K_ORIG;
    const int mrow = m0 + mbase + (lid >> 2);
    const int ncol = n0 + nbase + (lid & 3) * 2;
    #pragma unroll
    for (int im = 0; im < 2; im++) {
        #pragma unroll
        for (int in = 0; in < 4; in++) {
            const int m = mrow + im * 16;
            const int n = ncol + in * 8;
            const float b0 = __ldg(&bias[n]);
            const float b1 = __ldg(&bias[n + 1]);
            float2 v0, v1;
            v0.x = acc[im][in][0] * inv + b0;
            v0.y = acc[im][in][1] * inv + b1;
            v1.x = acc[im][in][2] * inv + b0;
            v1.y = acc[im][in][3] * inv + b1;
            *reinterpret_cast<float2*>(&out[(size_t)m * N_TOTAL + n]) = v0;
            *reinterpret_cast<float2*>(&out[(size_t)(m + 8) * N_TOTAL + n]) = v1;
        }
    }
}

// ---------------- launch ----------------
extern "C" void kernel_launch(void* const* d_in, const int* in_sizes, int n_in,
                              void* d_out, int out_size) {
    (void)in_sizes; (void)n_in; (void)out_size;
    const float* x    = (const float*)d_in[0];
    const float* e    = (const float*)d_in[1];
    const float* bias = (const float*)d_in[2];
    float* out = (float*)d_out;

    cudaFuncSetAttribute(gemm_fused_kernel,
                         cudaFuncAttributeMaxDynamicSharedMemorySize, SMEM_BYTES);

    convert_e_kernel<<<dim3(K_PAD / 32, N_TOTAL / 32), dim3(32, 8)>>>(e);
    gemm_fused_kernel<<<dim3(M_TOTAL / MT, N_TOTAL / NT), 256, SMEM_BYTES>>>(x, bias, out);
}

// round 4
// speedup vs baseline: 1.8791x; 1.8791x over previous
#include <cuda_runtime.h>
#include <cuda_fp16.h>
#include <cstdint>

// ---------------- problem constants ----------------
#define K_ORIG  20000
#define K_PAD   20032
#define M_TOTAL 2048
#define N_TOTAL 512
#define MT 128
#define NT 64
#define KT 64
#define NCHUNK (K_PAD / KT)      // 313
#define ZCHUNK0 157              // chunks for z==0; z==1 gets 156

#define A_BYTES (MT * KT * 2)    // 16384
#define B_BYTES (NT * KT * 2)    // 8192
#define STAGE   (A_BYTES + B_BYTES)
#define NSTAGE  4
#define SMEM_BYTES (1024 + NSTAGE * STAGE)   // 99328 -> 2 CTAs/SM fit

// ---------------- device scratch (fp16 operands) ----------------
__device__ __half g_xh[(size_t)M_TOTAL * K_PAD];   // x   [M, K_PAD] row-major
__device__ __half g_eh[(size_t)N_TOTAL * K_PAD];   // E^T [N, K_PAD] K-major

// ---------------- helpers ----------------
__device__ __forceinline__ uint32_t smem_u32(const void* p) {
    uint32_t a;
    asm("{ .reg .u64 t; cvta.to.shared.u64 t, %1; cvt.u32.u64 %0, t; }"
        : "=r"(a) : "l"(p));
    return a;
}

__device__ __forceinline__ uint32_t swz(uint32_t off) {
    return off ^ ((off >> 3) & 0x70u);     // 128B-period XOR swizzle
}

__device__ __forceinline__ void cp16(uint32_t sa, const void* gp) {
    asm volatile("cp.async.cg.shared.global [%0], [%1], 16;" :: "r"(sa), "l"(gp));
}

__device__ __forceinline__ void ldsm4(uint32_t* r, uint32_t sa) {
    asm volatile("ldmatrix.sync.aligned.m8n8.x4.shared.b16 {%0,%1,%2,%3}, [%4];"
                 : "=r"(r[0]), "=r"(r[1]), "=r"(r[2]), "=r"(r[3]) : "r"(sa));
}

__device__ __forceinline__ void mma16816(float* d, const uint32_t* a,
                                         const uint32_t* b) {
    asm volatile(
        "mma.sync.aligned.m16n8k16.row.col.f32.f16.f16.f32 "
        "{%0,%1,%2,%3}, {%4,%5,%6,%7}, {%8,%9}, {%0,%1,%2,%3};"
        : "+f"(d[0]), "+f"(d[1]), "+f"(d[2]), "+f"(d[3])
        : "r"(a[0]), "r"(a[1]), "r"(a[2]), "r"(a[3]), "r"(b[0]), "r"(b[1]));
}

// ---------------- conversion kernels ----------------
// x fp32 [M, 20000] -> fp16 [M, 20032] (zero-padded tail)
__global__ void convert_x_kernel(const float* __restrict__ x) {
    unsigned idx4 = blockIdx.x * 256u + threadIdx.x;
    const unsigned per_row = K_PAD / 4;             // 5008
    if (idx4 >= (unsigned)M_TOTAL * per_row) return;
    unsigned m = idx4 / per_row;
    unsigned k = (idx4 - m * per_row) * 4u;
    float4 v;
    if (k + 3 < K_ORIG) {
        v = *reinterpret_cast<const float4*>(x + (size_t)m * K_ORIG + k);
    } else {
        v.x = v.y = v.z = v.w = 0.0f;
    }
    __half2 h0 = __floats2half2_rn(v.x, v.y);
    __half2 h1 = __floats2half2_rn(v.z, v.w);
    uint2 pk;
    pk.x = *reinterpret_cast<uint32_t*>(&h0);
    pk.y = *reinterpret_cast<uint32_t*>(&h1);
    *reinterpret_cast<uint2*>(g_xh + (size_t)m * K_PAD + k) = pk;
}

// E fp32 [20000, 512] -> E^T fp16 [512, 20032] (K-major, zero-padded tail)
__global__ void convert_e_kernel(const float* __restrict__ e) {
    __shared__ float tile[32][33];
    const int kb = blockIdx.x * 32;
    const int hb = blockIdx.y * 32;
    const int tx = threadIdx.x, ty = threadIdx.y;
    #pragma unroll
    for (int i = ty; i < 32; i += 8) {
        int k = kb + i;
        tile[i][tx] = (k < K_ORIG) ? e[(size_t)k * N_TOTAL + hb + tx] : 0.0f;
    }
    __syncthreads();
    #pragma unroll
    for (int i = ty; i < 32; i += 8) {
        int h = hb + i;
        int k = kb + tx;
        g_eh[(size_t)h * K_PAD + k] = __float2half_rn(tile[tx][i]);
    }
}

// ---------------- fp16 mma.sync GEMM, split-K=2, 4-stage, 1 sync/chunk ----
// out[m, n] += partial( sum_k x[m,k] * E[k,n] ) / K_ORIG  (+ bias on z==0)
__global__ void __launch_bounds__(256, 2)
gemm_fp16_kernel(const float* __restrict__ bias, float* __restrict__ out) {
    extern __shared__ char smem_raw[];
    uint32_t sb = smem_u32(smem_raw);
    sb = (sb + 1023u) & ~1023u;

    const int tid = threadIdx.x;
    const int wid = tid >> 5;
    const int lid = tid & 31;
    const int m0 = blockIdx.x * MT;
    const int n0 = blockIdx.y * NT;
    const int zz = blockIdx.z;
    const int cbeg = zz ? ZCHUNK0 : 0;
    const int CN   = zz ? (NCHUNK - ZCHUNK0) : ZCHUNK0;

    const __half* __restrict__ xg = g_xh + (size_t)m0 * K_PAD;
    const __half* __restrict__ eg = g_eh + (size_t)n0 * K_PAD;

    // ---- producer indexing: 256 threads, 16B each ----
    const int c16 = tid & 7;        // 16B column within 128B row
    const int r32 = tid >> 3;       // 0..31

    auto load_chunk = [&](int il) {             // il = local chunk index
        if (il >= CN) return;
        const uint32_t st = sb + (uint32_t)(il & (NSTAGE - 1)) * (uint32_t)STAGE;
        const int k0 = (cbeg + il) * KT;
        #pragma unroll
        for (int i = 0; i < 4; i++) {          // A: 128 rows
            const int row = r32 + i * 32;
            const uint32_t sa = st + swz((uint32_t)(row * 128 + c16 * 16));
            cp16(sa, xg + (size_t)row * K_PAD + (k0 + c16 * 8));
        }
        #pragma unroll
        for (int i = 0; i < 2; i++) {          // B: 64 rows
            const int row = r32 + i * 32;
            const uint32_t sa = st + (uint32_t)A_BYTES
                              + swz((uint32_t)(row * 128 + c16 * 16));
            cp16(sa, eg + (size_t)row * K_PAD + (k0 + c16 * 8));
        }
        asm volatile("cp.async.commit_group;" ::: "memory");
    };

    // ---- consumer indexing ----
    const int wm = wid & 3;         // 4 warps along M
    const int wn = wid >> 2;        // 2 warps along N
    const int mbase = wm * 32;
    const int nbase = wn * 32;
    const int a_row   = mbase + (lid & 15);
    const uint32_t a_kh = (uint32_t)(lid >> 4) * 16u;
    const int b_row   = nbase + ((lid >> 4) * 8) + (lid & 7);
    const uint32_t b_kh = (uint32_t)((lid >> 3) & 1) * 16u;

    float acc[2][4][4];
    #pragma unroll
    for (int i = 0; i < 2; i++)
        #pragma unroll
        for (int j = 0; j < 4; j++)
            #pragma unroll
            for (int q = 0; q < 4; q++) acc[i][j][q] = 0.0f;

    // ---- preamble: 3 chunks in flight ----
    load_chunk(0);
    load_chunk(1);
    load_chunk(2);

    for (int il = 0; il < CN; il++) {
        // chunk il must be resident
        if (il + 2 < CN) {
            asm volatile("cp.async.wait_group 2;" ::: "memory");
        } else if (il + 1 < CN) {
            asm volatile("cp.async.wait_group 1;" ::: "memory");
        } else {
            asm volatile("cp.async.wait_group 0;" ::: "memory");
        }
        __syncthreads();   // stage (il+3)&3 == (il-1)&3: all readers of il-1 are past

        load_chunk(il + 3);

        const uint32_t st = sb + (uint32_t)(il & (NSTAGE - 1)) * (uint32_t)STAGE;
        #pragma unroll
        for (int ks = 0; ks < 4; ks++) {
            const uint32_t kb = (uint32_t)ks * 32u;
            uint32_t af[2][4];
            #pragma unroll
            for (int im = 0; im < 2; im++) {
                const uint32_t off = (uint32_t)((a_row + im * 16) * 128) + kb + a_kh;
                ldsm4(af[im], st + swz(off));
            }
            uint32_t bf[2][4];
            #pragma unroll
            for (int ib = 0; ib < 2; ib++) {
                const uint32_t off = (uint32_t)((b_row + ib * 16) * 128) + kb + b_kh;
                ldsm4(bf[ib], st + (uint32_t)A_BYTES + swz(off));
            }
            #pragma unroll
            for (int im = 0; im < 2; im++) {
                #pragma unroll
                for (int in = 0; in < 4; in++) {
                    mma16816(acc[im][in], af[im], &bf[in >> 1][(in & 1) * 2]);
                }
            }
        }
    }

    // ---- epilogue: atomic accumulate into zeroed output ----
    const float inv = 1.0f / (float)K_ORIG;
    const int mrow = m0 + mbase + (lid >> 2);
    const int ncol = n0 + nbase + (lid & 3) * 2;
    #pragma unroll
    for (int im = 0; im < 2; im++) {
        #pragma unroll
        for (int in = 0; in < 4; in++) {
            const int m = mrow + im * 16;
            const int n = ncol + in * 8;
            const float b0 = zz ? 0.0f : __ldg(&bias[n]);
            const float b1 = zz ? 0.0f : __ldg(&bias[n + 1]);
            atomicAdd(&out[(size_t)m * N_TOTAL + n],       acc[im][in][0] * inv + b0);
            atomicAdd(&out[(size_t)m * N_TOTAL + n + 1],   acc[im][in][1] * inv + b1);
            atomicAdd(&out[(size_t)(m + 8) * N_TOTAL + n],     acc[im][in][2] * inv + b0);
            atomicAdd(&out[(size_t)(m + 8) * N_TOTAL + n + 1], acc[im][in][3] * inv + b1);
        }
    }
}

// ---------------- launch ----------------
extern "C" void kernel_launch(void* const* d_in, const int* in_sizes, int n_in,
                              void* d_out, int out_size) {
    (void)in_sizes; (void)n_in;
    const float* x    = (const float*)d_in[0];
    const float* e    = (const float*)d_in[1];
    const float* bias = (const float*)d_in[2];
    float* out = (float*)d_out;

    cudaFuncSetAttribute(gemm_fp16_kernel,
                         cudaFuncAttributeMaxDynamicSharedMemorySize, SMEM_BYTES);

    cudaMemsetAsync(out, 0, (size_t)out_size * sizeof(float), 0);
    {
        int tot4 = M_TOTAL * (K_PAD / 4);
        convert_x_kernel<<<(tot4 + 255) / 256, 256>>>(x);
    }
    convert_e_kernel<<<dim3(K_PAD / 32, N_TOTAL / 32), dim3(32, 8)>>>(e);
    gemm_fp16_kernel<<<dim3(M_TOTAL / MT, N_TOTAL / NT, 2), 256, SMEM_BYTES>>>(bias, out);
}

// round 5
// speedup vs baseline: 2.0522x; 1.0921x over previous
#include <cuda_runtime.h>
#include <cuda_fp16.h>
#include <cstdint>

// ---------------- problem constants ----------------
#define K_ORIG  20000
#define K_PAD   20032
#define M_TOTAL 2048
#define N_TOTAL 512
#define MT 128
#define NT 64
#define KT 64
#define NCHUNK (K_PAD / KT)          // 313
#define TILES_M (M_TOTAL / MT)       // 16
#define TILES_N (N_TOTAL / NT)       // 8
#define TILES   (TILES_M * TILES_N)  // 128
#define WTOTAL  (TILES * NCHUNK)     // 40064
#define CTAS    296                  // 148 SMs x 2
#define WBASE   (WTOTAL / CTAS)      // 135
#define WREM    (WTOTAL - CTAS * WBASE) // 104

#define A_BYTES (MT * KT * 2)    // 16384
#define B_BYTES (NT * KT * 2)    // 8192
#define STAGE   (A_BYTES + B_BYTES)
#define NSTAGE  4
#define SMEM_BYTES (1024 + NSTAGE * STAGE)   // 99328 -> 2 CTAs/SM

// convert grid split
#define XBLOCKS (M_TOTAL * (K_PAD / 4) / 256)          // 40064
#define EKB     (K_PAD / 32)                           // 626
#define EBLOCKS (EKB * (N_TOTAL / 32))                 // 10016

// ---------------- device scratch (fp16 operands) ----------------
__device__ __half g_xh[(size_t)M_TOTAL * K_PAD];   // x   [M, K_PAD] row-major
__device__ __half g_eh[(size_t)N_TOTAL * K_PAD];   // E^T [N, K_PAD] K-major

// ---------------- helpers ----------------
__device__ __forceinline__ uint32_t smem_u32(const void* p) {
    uint32_t a;
    asm("{ .reg .u64 t; cvta.to.shared.u64 t, %1; cvt.u32.u64 %0, t; }"
        : "=r"(a) : "l"(p));
    return a;
}

__device__ __forceinline__ uint32_t swz(uint32_t off) {
    return off ^ ((off >> 3) & 0x70u);     // 128B-period XOR swizzle
}

__device__ __forceinline__ void cp16(uint32_t sa, const void* gp) {
    asm volatile("cp.async.cg.shared.global [%0], [%1], 16;" :: "r"(sa), "l"(gp));
}

__device__ __forceinline__ void ldsm4(uint32_t* r, uint32_t sa) {
    asm volatile("ldmatrix.sync.aligned.m8n8.x4.shared.b16 {%0,%1,%2,%3}, [%4];"
                 : "=r"(r[0]), "=r"(r[1]), "=r"(r[2]), "=r"(r[3]) : "r"(sa));
}

__device__ __forceinline__ void mma16816(float* d, const uint32_t* a,
                                         const uint32_t* b) {
    asm volatile(
        "mma.sync.aligned.m16n8k16.row.col.f32.f16.f16.f32 "
        "{%0,%1,%2,%3}, {%4,%5,%6,%7}, {%8,%9}, {%0,%1,%2,%3};"
        : "+f"(d[0]), "+f"(d[1]), "+f"(d[2]), "+f"(d[3])
        : "r"(a[0]), "r"(a[1]), "r"(a[2]), "r"(a[3]), "r"(b[0]), "r"(b[1]));
}

// ---------------- combined conversion kernel ----------------
__global__ void convert_all_kernel(const float* __restrict__ x,
                                   const float* __restrict__ e) {
    __shared__ float tile[32][33];
    if (blockIdx.x < XBLOCKS) {
        // x fp32 [M, 20000] -> fp16 [M, 20032] (zero-padded tail)
        unsigned idx4 = blockIdx.x * 256u + threadIdx.x;
        const unsigned per_row = K_PAD / 4;             // 5008
        unsigned m = idx4 / per_row;
        unsigned k = (idx4 - m * per_row) * 4u;
        float4 v;
        if (k + 3 < K_ORIG) {
            v = *reinterpret_cast<const float4*>(x + (size_t)m * K_ORIG + k);
        } else {
            v.x = v.y = v.z = v.w = 0.0f;
        }
        __half2 h0 = __floats2half2_rn(v.x, v.y);
        __half2 h1 = __floats2half2_rn(v.z, v.w);
        uint2 pk;
        pk.x = *reinterpret_cast<uint32_t*>(&h0);
        pk.y = *reinterpret_cast<uint32_t*>(&h1);
        *reinterpret_cast<uint2*>(g_xh + (size_t)m * K_PAD + k) = pk;
    } else {
        // E fp32 [20000, 512] -> E^T fp16 [512, 20032] K-major, zero-padded
        const int b  = blockIdx.x - XBLOCKS;
        const int kb = (b % EKB) * 32;
        const int hb = (b / EKB) * 32;
        const int tx = threadIdx.x & 31;
        const int ty = threadIdx.x >> 5;       // 0..7
        #pragma unroll
        for (int i = ty; i < 32; i += 8) {
            int k = kb + i;
            tile[i][tx] = (k < K_ORIG) ? e[(size_t)k * N_TOTAL + hb + tx] : 0.0f;
        }
        __syncthreads();
        #pragma unroll
        for (int i = ty; i < 32; i += 8) {
            int h = hb + i;
            int k = kb + tx;
            g_eh[(size_t)h * K_PAD + k] = __float2half_rn(tile[tx][i]);
        }
    }
}

// ---------------- stream-K fp16 mma.sync GEMM ----------------
// out[m, n] = (sum_k x[m,k] * E[k,n]) / K_ORIG + bias[n]  (RED-accumulated)
__global__ void __launch_bounds__(256, 2)
gemm_streamk_kernel(const float* __restrict__ bias, float* __restrict__ out) {
    extern __shared__ char smem_raw[];
    uint32_t sb = smem_u32(smem_raw);
    sb = (sb + 1023u) & ~1023u;

    const int tid = threadIdx.x;
    const int wid = tid >> 5;
    const int lid = tid & 31;

    // ---- work range ----
    const int bi   = blockIdx.x;
    const int wbeg = bi * WBASE + (bi < WREM ? bi : WREM);
    const int CN   = WBASE + (bi < WREM ? 1 : 0);

    int ct = wbeg / NCHUNK;        // consumer tile
    int cc = wbeg - ct * NCHUNK;   // consumer chunk within tile
    int pt = ct, pc = cc;          // prefetch tile/chunk

    // ---- producer indexing: 256 threads, 16B each ----
    const int c16 = tid & 7;
    const int r32 = tid >> 3;

    auto load_next = [&](int il) {             // il = local load index (stage)
        const uint32_t st = sb + (uint32_t)(il & (NSTAGE - 1)) * (uint32_t)STAGE;
        const int k0 = pc * KT;
        const __half* xg = g_xh + (size_t)((pt >> 3) * MT) * K_PAD;
        const __half* eg = g_eh + (size_t)((pt & 7) * NT) * K_PAD;
        #pragma unroll
        for (int i = 0; i < 4; i++) {          // A: 128 rows
            const int row = r32 + i * 32;
            const uint32_t sa = st + swz((uint32_t)(row * 128 + c16 * 16));
            cp16(sa, xg + (size_t)row * K_PAD + (k0 + c16 * 8));
        }
        #pragma unroll
        for (int i = 0; i < 2; i++) {          // B: 64 rows
            const int row = r32 + i * 32;
            const uint32_t sa = st + (uint32_t)A_BYTES
                              + swz((uint32_t)(row * 128 + c16 * 16));
            cp16(sa, eg + (size_t)row * K_PAD + (k0 + c16 * 8));
        }
        asm volatile("cp.async.commit_group;" ::: "memory");
        if (++pc == NCHUNK) { pc = 0; pt++; }
    };

    // ---- consumer indexing ----
    const int wm = wid & 3;
    const int wn = wid >> 2;
    const int mbase = wm * 32;
    const int nbase = wn * 32;
    const int a_row = mbase + (lid & 15);
    const uint32_t a_kh = (uint32_t)(lid >> 4) * 16u;
    const int b_row = nbase + ((lid >> 4) * 8) + (lid & 7);
    const uint32_t b_kh = (uint32_t)((lid >> 3) & 1) * 16u;

    float acc[2][4][4];
    #pragma unroll
    for (int i = 0; i < 2; i++)
        #pragma unroll
        for (int j = 0; j < 4; j++)
            #pragma unroll
            for (int q = 0; q < 4; q++) acc[i][j][q] = 0.0f;

    const float inv = 1.0f / (float)K_ORIG;
    const int erow = mbase + (lid >> 2);
    const int ecol = nbase + (lid & 3) * 2;

    auto epilogue = [&](int t, bool addb) {
        const int m0 = (t >> 3) * MT;
        const int n0 = (t & 7) * NT;
        #pragma unroll
        for (int im = 0; im < 2; im++) {
            #pragma unroll
            for (int in = 0; in < 4; in++) {
                const int m = m0 + erow + im * 16;
                const int n = n0 + ecol + in * 8;
                const float b0 = addb ? __ldg(&bias[n]) : 0.0f;
                const float b1 = addb ? __ldg(&bias[n + 1]) : 0.0f;
                atomicAdd(&out[(size_t)m * N_TOTAL + n],           acc[im][in][0] * inv + b0);
                atomicAdd(&out[(size_t)m * N_TOTAL + n + 1],       acc[im][in][1] * inv + b1);
                atomicAdd(&out[(size_t)(m + 8) * N_TOTAL + n],     acc[im][in][2] * inv + b0);
                atomicAdd(&out[(size_t)(m + 8) * N_TOTAL + n + 1], acc[im][in][3] * inv + b1);
                acc[im][in][0] = 0.0f; acc[im][in][1] = 0.0f;
                acc[im][in][2] = 0.0f; acc[im][in][3] = 0.0f;
            }
        }
    };

    // ---- preamble: 3 chunks in flight ----
    load_next(0);
    if (CN > 1) load_next(1);
    if (CN > 2) load_next(2);

    bool addb = (cc == 0);     // this CTA owns chunk 0 of tile ct?

    for (int il = 0; il < CN; il++) {
        if (il + 2 < CN) {
            asm volatile("cp.async.wait_group 2;" ::: "memory");
        } else if (il + 1 < CN) {
            asm volatile("cp.async.wait_group 1;" ::: "memory");
        } else {
            asm volatile("cp.async.wait_group 0;" ::: "memory");
        }
        __syncthreads();

        if (il + 3 < CN) load_next(il + 3);

        const uint32_t st = sb + (uint32_t)(il & (NSTAGE - 1)) * (uint32_t)STAGE;
        #pragma unroll
        for (int ks = 0; ks < 4; ks++) {
            const uint32_t kb = (uint32_t)ks * 32u;
            uint32_t af[2][4];
            #pragma unroll
            for (int im = 0; im < 2; im++) {
                const uint32_t off = (uint32_t)((a_row + im * 16) * 128) + kb + a_kh;
                ldsm4(af[im], st + swz(off));
            }
            uint32_t bf[2][4];
            #pragma unroll
            for (int ib = 0; ib < 2; ib++) {
                const uint32_t off = (uint32_t)((b_row + ib * 16) * 128) + kb + b_kh;
                ldsm4(bf[ib], st + (uint32_t)A_BYTES + swz(off));
            }
            #pragma unroll
            for (int im = 0; im < 2; im++) {
                #pragma unroll
                for (int in = 0; in < 4; in++) {
                    mma16816(acc[im][in], af[im], &bf[in >> 1][(in & 1) * 2]);
                }
            }
        }

        // tile boundary or end of range -> flush partial
        if (cc == NCHUNK - 1 || il == CN - 1) {
            epilogue(ct, addb);
            ct++; cc = 0; addb = true;
        } else {
            cc++;
        }
    }
}

// ---------------- launch ----------------
extern "C" void kernel_launch(void* const* d_in, const int* in_sizes, int n_in,
                              void* d_out, int out_size) {
    (void)in_sizes; (void)n_in;
    const float* x    = (const float*)d_in[0];
    const float* e    = (const float*)d_in[1];
    const float* bias = (const float*)d_in[2];
    float* out = (float*)d_out;

    cudaFuncSetAttribute(gemm_streamk_kernel,
                         cudaFuncAttributeMaxDynamicSharedMemorySize, SMEM_BYTES);

    cudaMemsetAsync(out, 0, (size_t)out_size * sizeof(float), 0);
    convert_all_kernel<<<XBLOCKS + EBLOCKS, 256>>>(x, e);
    gemm_streamk_kernel<<<CTAS, 256, SMEM_BYTES>>>(bias, out);
}